// round 12
// baseline (speedup 1.0000x reference)
#include <cuda_runtime.h>
#include <cstddef>

#define TT 64
#define LL 512
#define BB 512
#define START_TAG 62
#define STOP_TAG  63
#define WPB 8                  // warps (sequences) per block -> 2 per SMSP
#define NBLK (BB / WPB)        // 64 blocks

// Scratch (allocation-free requirement).
__device__ float g_partials[BB];
__device__ int   g_count;      // zero-init; reset by last block each launch

#define FULLMASK 0xffffffffu

__device__ __forceinline__ void fma2(unsigned long long& acc,
                                     unsigned long long p,
                                     unsigned long long q) {
    asm("fma.rn.f32x2 %0, %1, %2, %0;" : "+l"(acc) : "l"(p), "l"(q));
}
__device__ __forceinline__ void add2(unsigned long long& a, unsigned long long b) {
    asm("add.rn.f32x2 %0, %0, %1;" : "+l"(a) : "l"(b));
}
__device__ __forceinline__ float2 unpack2(unsigned long long v) {
    float2 r;
    asm("mov.b64 {%0, %1}, %2;" : "=f"(r.x), "=f"(r.y) : "l"(v));
    return r;
}
__device__ __forceinline__ unsigned long long pack2(float lo, float hi) {
    unsigned long long v;
    asm("mov.b64 %0, {%1, %2};" : "=l"(v) : "f"(lo), "f"(hi));
    return v;
}

__device__ __forceinline__ float warp_sum(float v) {
#pragma unroll
    for (int o = 16; o > 0; o >>= 1) v += __shfl_xor_sync(FULLMASK, v, o);
    return v;
}
__device__ __forceinline__ float warp_max(float v) {
#pragma unroll
    for (int o = 16; o > 0; o >>= 1) v = fmaxf(v, __shfl_xor_sync(FULLMASK, v, o));
    return v;
}

// Dual 64-dot for this thread's two output tags (rows in P2a / P2b).
__device__ __forceinline__ void dot64_pair(const float* __restrict__ qbuf,
                                           const unsigned long long* __restrict__ P2a,
                                           const unsigned long long* __restrict__ P2b,
                                           float& s0, float& s1) {
    const ulonglong2* q4 = (const ulonglong2*)qbuf;
    unsigned long long a0 = 0, a1 = 0, b0 = 0, b1 = 0;
#pragma unroll
    for (int k = 0; k < 16; ++k) {
        ulonglong2 v = q4[k];
        fma2(a0, P2a[2 * k],     v.x);
        fma2(a1, P2a[2 * k + 1], v.y);
        fma2(b0, P2b[2 * k],     v.x);
        fma2(b1, P2b[2 * k + 1], v.y);
    }
    add2(a0, a1);
    add2(b0, b1);
    float2 pa = unpack2(a0);
    float2 pb = unpack2(b0);
    s0 = pa.x + pa.y;
    s1 = pb.x + pb.y;
}

__global__ void __launch_bounds__(32 * WPB, 1) crf_fused_kernel(
    const float* __restrict__ inputs,   // (B, L, T)
    const int*   __restrict__ tags,     // (B, L)
    const int*   __restrict__ mask,     // (B, L)
    const float* __restrict__ trans,    // (T, T)
    float*       __restrict__ out)
{
    const int tid  = threadIdx.x;
    const int wid  = tid >> 5;
    const int l    = tid & 31;          // owns tags 2l, 2l+1
    const int i0   = 2 * l;
    const int i1   = 2 * l + 1;
    const int seq  = blockIdx.x * WPB + wid;

    __shared__ __align__(16) float q_sh[WPB][2][TT];  // per-warp double buffer
    __shared__ float rf[32 * WPB];
    __shared__ int   islast;

    // Packed exp(transition) rows for this thread's two destination tags.
    unsigned long long P2a[TT / 2], P2b[TT / 2];
#pragma unroll
    for (int j = 0; j < TT / 2; ++j) {
        P2a[j] = pack2(__expf(trans[i0 * TT + 2 * j]), __expf(trans[i0 * TT + 2 * j + 1]));
        P2b[j] = pack2(__expf(trans[i1 * TT + 2 * j]), __expf(trans[i1 * TT + 2 * j + 1]));
    }

    // all-ones mask detection for this warp's sequence (warp-local).
    int m_and = 1;
    for (int t = l; t < LL; t += 32)
        m_and &= (mask[seq * LL + t] != 0);
    const int all_ones = __all_sync(FULLMASK, m_and);

    // Emissions as float2 (tags 2l, 2l+1 are contiguous): 32 float2 per step.
    const float2* ep2 = (const float2*)(inputs + (size_t)seq * LL * TT) + l;

    float a0, a1, C;

    if (all_ones) {
        // ===== fast path: prob-space recursion, warp-synchronous =============
        ((float2*)q_sh[wid][0])[l] =
            make_float2((i0 == START_TAG) ? 1.0f : 0.0f,
                        (i1 == START_TAG) ? 1.0f : 0.0f);

        float2 e0 = ep2[0 * 32], e1 = ep2[1 * 32], e2 = ep2[2 * 32], e3 = ep2[3 * 32];
        int Dint = 0;
        __syncwarp();

#pragma unroll 4
        for (int t = 0; t < LL; ++t) {
            float2 e_pf = (t + 4 < LL) ? ep2[(t + 4) * 32] : make_float2(0.f, 0.f);

            const float E0 = __expf(e0.x);
            const float E1 = __expf(e0.y);

            const int bu = t & 1;
            const float* qb = q_sh[wid][bu];

            // Power-of-two renorm from q[0]'s exponent field (ALU only).
            const float q0 = qb[0];
            const unsigned ebits = __float_as_uint(q0) & 0x7f800000u;
            const float r = ebits ? __uint_as_float(0x7f000000u - ebits) : 1.0f;
            Dint += ebits ? ((int)(ebits >> 23) - 127) : 0;
            const float m0 = E0 * r;
            const float m1 = E1 * r;

            float s0, s1;
            dot64_pair(qb, P2a, P2b, s0, s1);
            ((float2*)q_sh[wid][bu ^ 1])[l] = make_float2(s0 * m0, s1 * m1);
            __syncwarp();

            e0 = e1; e1 = e2; e2 = e3; e3 = e_pf;
        }

        const float2 qf = ((const float2*)q_sh[wid][0])[l];
        a0 = (qf.x > 0.0f) ? __logf(qf.x) : -1.0e30f;
        a1 = (qf.y > 0.0f) ? __logf(qf.y) : -1.0e30f;
        C  = (float)Dint * 0.6931471805599453f;
    } else {
        // ===== general masked path (log space; rare, correctness-first) ======
        a0 = (i0 == START_TAG) ? 0.0f : -10000.0f;
        a1 = (i1 == START_TAG) ? 0.0f : -10000.0f;
        C  = 0.0f;
        for (int t = 0; t < LL; ++t) {
            const int bu = t & 1;
            ((float2*)q_sh[wid][bu])[l] = make_float2(__expf(a0), __expf(a1));
            __syncwarp();
            const float* qb = q_sh[wid][bu];

            const float mf = (float)mask[seq * LL + t];
            float s0, s1;
            if (mf != 0.0f) {
                dot64_pair(qb, P2a, P2b, s0, s1);
            } else {
                float acc = 0.f;
#pragma unroll
                for (int j = 0; j < TT; ++j) acc += qb[j];
                s0 = s1 = acc;
            }

            const float2 e = ep2[t * 32];
            float d0 = fmaf(mf, e.x, __logf(s0));
            float d1 = fmaf(mf, e.y, __logf(s1));
            d0 = fmaxf(d0, -1.0e30f);
            d1 = fmaxf(d1, -1.0e30f);
            const float anchor = __shfl_sync(FULLMASK, d0, 0);  // d of tag 0
            a0 = d0 - anchor;
            a1 = d1 - anchor;
            C += anchor;
            __syncwarp();
        }
    }

    // ============== per-sequence finale (all warp-local, shuffle-based) ======
    float t0 = fmaxf(a0 + trans[STOP_TAG * TT + i0], -1.0e30f);
    float t1 = fmaxf(a1 + trans[STOP_TAG * TT + i1], -1.0e30f);
    const float mx = warp_max(fmaxf(t0, t1));
    const float sm = warp_sum(__expf(t0 - mx) + __expf(t1 - mx));
    const float logden = C + mx + __logf(sm);

    // numerator path score (gold tags)
    float sc = 0.f;
    const float* in_b = inputs + (size_t)seq * LL * TT;
    const int*   tg   = tags + seq * LL;
    const int*   mk   = mask + seq * LL;
    for (int t = l; t < LL - 1; t += 32) {
        const int pt = tg[t];
        const int nt = tg[t + 1];
        sc += trans[nt * TT + pt] * (float)mk[t + 1]
            + in_b[t * TT + pt] * (float)mk[t];
    }
    sc = warp_sum(sc);
    if (l == 0) {
        const int tfirst = tg[0];
        const int tlast  = tg[LL - 1];
        float score = sc
                    + trans[tfirst * TT + START_TAG]
                    + trans[STOP_TAG * TT + tlast]
                    + in_b[(LL - 1) * TT + tlast] * (float)mk[LL - 1];
        g_partials[seq] = score - logden;
    }

    // ---- deterministic fixed-order final reduction in the last block ----
    __syncthreads();
    if (tid == 0) {
        __threadfence();
        int old = atomicAdd(&g_count, 1);
        islast = (old == (int)gridDim.x - 1);
    }
    __syncthreads();
    if (islast) {
        __threadfence();
        float s = 0.f;
#pragma unroll
        for (int k = 0; k < BB / (32 * WPB); ++k)      // fixed order: 2 adds
            s += g_partials[tid * (BB / (32 * WPB)) + k];
        rf[tid] = s;
        __syncthreads();
#pragma unroll
        for (int off = (32 * WPB) / 2; off > 0; off >>= 1) {
            if (tid < off) rf[tid] += rf[tid + off];
            __syncthreads();
        }
        if (tid == 0) {
            out[0] = rf[0];
            g_count = 0;
        }
    }
}

extern "C" void kernel_launch(void* const* d_in, const int* in_sizes, int n_in,
                              void* d_out, int out_size)
{
    const float* inputs = (const float*)d_in[0];
    const int*   tags   = (const int*)d_in[1];
    const int*   mask   = (const int*)d_in[2];
    const float* trans  = (const float*)d_in[3];

    crf_fused_kernel<<<NBLK, 32 * WPB>>>(inputs, tags, mask, trans, (float*)d_out);
}

// round 13
// speedup vs baseline: 1.1975x; 1.1975x over previous
#include <cuda_runtime.h>
#include <cstddef>

#define TT 64
#define LL 512
#define BB 512
#define START_TAG 62
#define STOP_TAG  63
#define WPB 4                  // warps (sequences) per block -> 1 per SMSP
#define NBLK (BB / WPB)        // 128 blocks

// Scratch (allocation-free requirement).
__device__ float g_partials[BB];
__device__ int   g_count;      // zero-init; reset by last block each launch

#define FULLMASK 0xffffffffu

__device__ __forceinline__ void fma2(unsigned long long& acc,
                                     unsigned long long p,
                                     unsigned long long q) {
    asm("fma.rn.f32x2 %0, %1, %2, %0;" : "+l"(acc) : "l"(p), "l"(q));
}
__device__ __forceinline__ void add2(unsigned long long& a, unsigned long long b) {
    asm("add.rn.f32x2 %0, %0, %1;" : "+l"(a) : "l"(b));
}
__device__ __forceinline__ float2 unpack2(unsigned long long v) {
    float2 r;
    asm("mov.b64 {%0, %1}, %2;" : "=f"(r.x), "=f"(r.y) : "l"(v));
    return r;
}
__device__ __forceinline__ unsigned long long pack2(float lo, float hi) {
    unsigned long long v;
    asm("mov.b64 %0, {%1, %2};" : "=l"(v) : "f"(lo), "f"(hi));
    return v;
}

__device__ __forceinline__ float warp_sum(float v) {
#pragma unroll
    for (int o = 16; o > 0; o >>= 1) v += __shfl_xor_sync(FULLMASK, v, o);
    return v;
}
__device__ __forceinline__ float warp_max(float v) {
#pragma unroll
    for (int o = 16; o > 0; o >>= 1) v = fmaxf(v, __shfl_xor_sync(FULLMASK, v, o));
    return v;
}

__global__ void __launch_bounds__(32 * WPB, 1) crf_fused_kernel(
    const float* __restrict__ inputs,   // (B, L, T)
    const int*   __restrict__ tags,     // (B, L)
    const int*   __restrict__ mask,     // (B, L)
    const float* __restrict__ trans,    // (T, T)
    float*       __restrict__ out)
{
    const int tid  = threadIdx.x;
    const int wid  = tid >> 5;
    const int l    = tid & 31;          // owns tags 2l, 2l+1
    const int i0   = 2 * l;
    const int i1   = 2 * l + 1;
    const int seq  = blockIdx.x * WPB + wid;

    __shared__ float rf[32 * WPB];
    __shared__ int   islast;

    // Packed exp(transition) rows for this thread's two destination tags.
    // P2a[k] = (expT[i0, 2k], expT[i0, 2k+1]) — pairs with lane k's q-pair.
    unsigned long long P2a[TT / 2], P2b[TT / 2];
#pragma unroll
    for (int j = 0; j < TT / 2; ++j) {
        P2a[j] = pack2(__expf(trans[i0 * TT + 2 * j]), __expf(trans[i0 * TT + 2 * j + 1]));
        P2b[j] = pack2(__expf(trans[i1 * TT + 2 * j]), __expf(trans[i1 * TT + 2 * j + 1]));
    }

    // all-ones mask detection for this warp's sequence (warp-local).
    int m_and = 1;
    for (int t = l; t < LL; t += 32)
        m_and &= (mask[seq * LL + t] != 0);
    const int all_ones = __all_sync(FULLMASK, m_and);

    // Emissions as float2 (tags 2l, 2l+1 contiguous): 32 float2 per step.
    const float2* ep2 = (const float2*)(inputs + (size_t)seq * LL * TT) + l;

    float a0, a1, C;

    if (all_ones) {
        // ===== fast path: prob-space recursion, shuffle-exchanged ============
        // q lives in registers: lane l holds (q[2l], q[2l+1]). Exchange by
        // 64 SHFL broadcasts that dual-issue into FFMA2 rt-3 gaps. No smem,
        // no syncwarp — shfl_sync IS the synchronization.
        float2 qp = make_float2((i0 == START_TAG) ? 1.0f : 0.0f,
                                (i1 == START_TAG) ? 1.0f : 0.0f);

        float2 e0 = ep2[0 * 32], e1 = ep2[1 * 32], e2 = ep2[2 * 32], e3 = ep2[3 * 32];
        int Dint = 0;

#pragma unroll 4
        for (int t = 0; t < LL; ++t) {
            float2 e_pf = (t + 4 < LL) ? ep2[(t + 4) * 32] : make_float2(0.f, 0.f);

            const float E0 = __expf(e0.x);   // off-chain (ring slot loaded 4 steps ago)
            const float E1 = __expf(e0.y);

            unsigned long long A0 = 0, A1 = 0, B0 = 0, B1 = 0;
            float q0_anchor = 0.0f;
#pragma unroll
            for (int k = 0; k < 32; ++k) {
                const float qx = __shfl_sync(FULLMASK, qp.x, k);
                const float qy = __shfl_sync(FULLMASK, qp.y, k);
                const unsigned long long qk = pack2(qx, qy);
                if (k == 0) q0_anchor = qx;
                if (k & 1) { fma2(A1, P2a[k], qk); fma2(B1, P2b[k], qk); }
                else       { fma2(A0, P2a[k], qk); fma2(B0, P2b[k], qk); }
            }
            add2(A0, A1);
            add2(B0, B1);
            const float2 pa = unpack2(A0);
            const float2 pb = unpack2(B0);
            const float sa = pa.x + pa.y;
            const float sb = pb.x + pb.y;

            // Power-of-two renorm from q[0]'s exponent field (ALU only).
            const unsigned ebits = __float_as_uint(q0_anchor) & 0x7f800000u;
            const float r = ebits ? __uint_as_float(0x7f000000u - ebits) : 1.0f;
            Dint += ebits ? ((int)(ebits >> 23) - 127) : 0;

            qp = make_float2(sa * (E0 * r), sb * (E1 * r));

            e0 = e1; e1 = e2; e2 = e3; e3 = e_pf;
        }

        a0 = (qp.x > 0.0f) ? __logf(qp.x) : -1.0e30f;
        a1 = (qp.y > 0.0f) ? __logf(qp.y) : -1.0e30f;
        C  = (float)Dint * 0.6931471805599453f;
    } else {
        // ===== general masked path (log space; rare, correctness-first) ======
        a0 = (i0 == START_TAG) ? 0.0f : -10000.0f;
        a1 = (i1 == START_TAG) ? 0.0f : -10000.0f;
        C  = 0.0f;
        for (int t = 0; t < LL; ++t) {
            const float2 qp = make_float2(__expf(a0), __expf(a1));
            const float mf = (float)mask[seq * LL + t];

            unsigned long long A0 = 0, A1 = 0, B0 = 0, B1 = 0;
            float qsum = 0.0f;
#pragma unroll
            for (int k = 0; k < 32; ++k) {
                const float qx = __shfl_sync(FULLMASK, qp.x, k);
                const float qy = __shfl_sync(FULLMASK, qp.y, k);
                const unsigned long long qk = pack2(qx, qy);
                qsum += qx + qy;
                if (k & 1) { fma2(A1, P2a[k], qk); fma2(B1, P2b[k], qk); }
                else       { fma2(A0, P2a[k], qk); fma2(B0, P2b[k], qk); }
            }
            add2(A0, A1);
            add2(B0, B1);
            const float2 pa = unpack2(A0);
            const float2 pb = unpack2(B0);
            float s0, s1;
            if (mf != 0.0f) { s0 = pa.x + pa.y; s1 = pb.x + pb.y; }
            else            { s0 = qsum;        s1 = qsum;        }

            const float2 e = ep2[t * 32];
            float d0 = fmaf(mf, e.x, __logf(s0));
            float d1 = fmaf(mf, e.y, __logf(s1));
            d0 = fmaxf(d0, -1.0e30f);
            d1 = fmaxf(d1, -1.0e30f);
            const float anchor = __shfl_sync(FULLMASK, d0, 0);  // d of tag 0
            a0 = d0 - anchor;
            a1 = d1 - anchor;
            C += anchor;
        }
    }

    // ============== per-sequence finale (all warp-local, shuffle-based) ======
    float t0 = fmaxf(a0 + trans[STOP_TAG * TT + i0], -1.0e30f);
    float t1 = fmaxf(a1 + trans[STOP_TAG * TT + i1], -1.0e30f);
    const float mx = warp_max(fmaxf(t0, t1));
    const float sm = warp_sum(__expf(t0 - mx) + __expf(t1 - mx));
    const float logden = C + mx + __logf(sm);

    // numerator path score (gold tags)
    float sc = 0.f;
    const float* in_b = inputs + (size_t)seq * LL * TT;
    const int*   tg   = tags + seq * LL;
    const int*   mk   = mask + seq * LL;
    for (int t = l; t < LL - 1; t += 32) {
        const int pt = tg[t];
        const int nt = tg[t + 1];
        sc += trans[nt * TT + pt] * (float)mk[t + 1]
            + in_b[t * TT + pt] * (float)mk[t];
    }
    sc = warp_sum(sc);
    if (l == 0) {
        const int tfirst = tg[0];
        const int tlast  = tg[LL - 1];
        float score = sc
                    + trans[tfirst * TT + START_TAG]
                    + trans[STOP_TAG * TT + tlast]
                    + in_b[(LL - 1) * TT + tlast] * (float)mk[LL - 1];
        g_partials[seq] = score - logden;
    }

    // ---- deterministic fixed-order final reduction in the last block ----
    __syncthreads();
    if (tid == 0) {
        __threadfence();
        int old = atomicAdd(&g_count, 1);
        islast = (old == (int)gridDim.x - 1);
    }
    __syncthreads();
    if (islast) {
        __threadfence();
        float s = 0.f;
#pragma unroll
        for (int k = 0; k < BB / (32 * WPB); ++k)      // fixed order: 4 adds
            s += g_partials[tid * (BB / (32 * WPB)) + k];
        rf[tid] = s;
        __syncthreads();
#pragma unroll
        for (int off = (32 * WPB) / 2; off > 0; off >>= 1) {
            if (tid < off) rf[tid] += rf[tid + off];
            __syncthreads();
        }
        if (tid == 0) {
            out[0] = rf[0];
            g_count = 0;
        }
    }
}

extern "C" void kernel_launch(void* const* d_in, const int* in_sizes, int n_in,
                              void* d_out, int out_size)
{
    const float* inputs = (const float*)d_in[0];
    const int*   tags   = (const int*)d_in[1];
    const int*   mask   = (const int*)d_in[2];
    const float* trans  = (const float*)d_in[3];

    crf_fused_kernel<<<NBLK, 32 * WPB>>>(inputs, tags, mask, trans, (float*)d_out);
}

// round 14
// speedup vs baseline: 1.6687x; 1.3935x over previous
#include <cuda_runtime.h>
#include <cstddef>

#define TT 64
#define LL 512
#define BB 512
#define START_TAG 62
#define STOP_TAG  63
#define SPB 4                  // sequences per block (8 warps: 4 fwd + 4 bwd)
#define NBLK (BB / SPB)        // 128 blocks
#define HALF (LL / 2)          // 256 steps per half-chain
#define LN2F 0.6931471805599453f

// Scratch (allocation-free requirement).
__device__ float g_partials[BB];
__device__ int   g_count;      // zero-init; reset by last block each launch

#define FULLMASK 0xffffffffu

__device__ __forceinline__ void fma2(unsigned long long& acc,
                                     unsigned long long p,
                                     unsigned long long q) {
    asm("fma.rn.f32x2 %0, %1, %2, %0;" : "+l"(acc) : "l"(p), "l"(q));
}
__device__ __forceinline__ void add2(unsigned long long& a, unsigned long long b) {
    asm("add.rn.f32x2 %0, %0, %1;" : "+l"(a) : "l"(b));
}
__device__ __forceinline__ float2 unpack2(unsigned long long v) {
    float2 r;
    asm("mov.b64 {%0, %1}, %2;" : "=f"(r.x), "=f"(r.y) : "l"(v));
    return r;
}
__device__ __forceinline__ unsigned long long pack2(float lo, float hi) {
    unsigned long long v;
    asm("mov.b64 %0, {%1, %2};" : "=l"(v) : "f"(lo), "f"(hi));
    return v;
}

__device__ __forceinline__ float warp_sum(float v) {
#pragma unroll
    for (int o = 16; o > 0; o >>= 1) v += __shfl_xor_sync(FULLMASK, v, o);
    return v;
}
__device__ __forceinline__ float warp_max(float v) {
#pragma unroll
    for (int o = 16; o > 0; o >>= 1) v = fmaxf(v, __shfl_xor_sync(FULLMASK, v, o));
    return v;
}

// Dual 64-dot for this thread's two output tags (weight rows P2a / P2b).
// P2x[m] pairs with smem inputs (2m, 2m+1).
__device__ __forceinline__ void dot64_pair(const float* __restrict__ qbuf,
                                           const unsigned long long* __restrict__ P2a,
                                           const unsigned long long* __restrict__ P2b,
                                           float& s0, float& s1) {
    const ulonglong2* q4 = (const ulonglong2*)qbuf;
    unsigned long long a0 = 0, a1 = 0, b0 = 0, b1 = 0;
#pragma unroll
    for (int k = 0; k < 16; ++k) {
        ulonglong2 v = q4[k];
        fma2(a0, P2a[2 * k],     v.x);
        fma2(a1, P2a[2 * k + 1], v.y);
        fma2(b0, P2b[2 * k],     v.x);
        fma2(b1, P2b[2 * k + 1], v.y);
    }
    add2(a0, a1);
    add2(b0, b1);
    float2 pa = unpack2(a0);
    float2 pb = unpack2(b0);
    s0 = pa.x + pa.y;
    s1 = pb.x + pb.y;
}

__global__ void __launch_bounds__(64 * SPB, 1) crf_fused_kernel(
    const float* __restrict__ inputs,   // (B, L, T)
    const int*   __restrict__ tags,     // (B, L)
    const int*   __restrict__ mask,     // (B, L)
    const float* __restrict__ trans,    // (T, T)
    float*       __restrict__ out)
{
    const int tid  = threadIdx.x;
    const int wid  = tid >> 5;
    const int l    = tid & 31;          // owns tags 2l, 2l+1
    const int i0   = 2 * l;
    const int i1   = 2 * l + 1;
    const int isFwd = (wid < SPB);
    const int sw   = wid & (SPB - 1);
    const int seq  = blockIdx.x * SPB + sw;

    __shared__ __align__(16) float q_sh[2 * SPB][2][TT];  // per-warp double buffer
    __shared__ int   Db_sh[2 * SPB];
    __shared__ float rf[64 * SPB];
    __shared__ int   islast;

    // Weight registers:
    //  fwd warp: rows i0,i1 of M (M[i,j] = exp(trans[i*64+j]))
    //  bwd warp: columns i0,i1 of M (for beta_prev[j] = sum_i M[i,j] v[i])
    unsigned long long P2a[TT / 2], P2b[TT / 2];
    if (isFwd) {
#pragma unroll
        for (int j = 0; j < TT / 2; ++j) {
            P2a[j] = pack2(__expf(trans[i0 * TT + 2 * j]), __expf(trans[i0 * TT + 2 * j + 1]));
            P2b[j] = pack2(__expf(trans[i1 * TT + 2 * j]), __expf(trans[i1 * TT + 2 * j + 1]));
        }
    } else {
#pragma unroll
        for (int j = 0; j < TT / 2; ++j) {
            P2a[j] = pack2(__expf(trans[(2 * j) * TT + i0]), __expf(trans[(2 * j + 1) * TT + i0]));
            P2b[j] = pack2(__expf(trans[(2 * j) * TT + i1]), __expf(trans[(2 * j + 1) * TT + i1]));
        }
    }

    // all-ones mask detection for this warp's sequence (warp-local).
    int m_and = 1;
    for (int t = l; t < LL; t += 32)
        m_and &= (mask[seq * LL + t] != 0);
    const int all_ones = __all_sync(FULLMASK, m_and);

    // Emissions as float2 (tags 2l, 2l+1 contiguous): 32 float2 per step.
    const float2* ep2 = (const float2*)(inputs + (size_t)seq * LL * TT) + l;

    float a0 = 0.f, a1 = 0.f, C = 0.f;  // general-path outputs
    int Dint = 0;                       // fast-path pow2 offset

    if (all_ones) {
        if (isFwd) {
            // ===== forward half: consume E_0..E_255 (R11 step body) ==========
            ((float2*)q_sh[wid][0])[l] =
                make_float2((i0 == START_TAG) ? 1.0f : 0.0f,
                            (i1 == START_TAG) ? 1.0f : 0.0f);

            float2 e0 = ep2[0 * 32], e1 = ep2[1 * 32], e2 = ep2[2 * 32], e3 = ep2[3 * 32];
            __syncwarp();

#pragma unroll 4
            for (int t = 0; t < HALF; ++t) {
                float2 e_pf = (t + 4 < HALF) ? ep2[(t + 4) * 32] : make_float2(0.f, 0.f);

                const float E0 = __expf(e0.x);
                const float E1 = __expf(e0.y);

                const int bu = t & 1;
                const float* qb = q_sh[wid][bu];

                const float q0 = qb[0];
                const unsigned ebits = __float_as_uint(q0) & 0x7f800000u;
                const float r = ebits ? __uint_as_float(0x7f000000u - ebits) : 1.0f;
                Dint += ebits ? ((int)(ebits >> 23) - 127) : 0;

                float s0, s1;
                dot64_pair(qb, P2a, P2b, s0, s1);
                ((float2*)q_sh[wid][bu ^ 1])[l] = make_float2(s0 * (E0 * r), s1 * (E1 * r));
                __syncwarp();

                e0 = e1; e1 = e2; e2 = e3; e3 = e_pf;
            }
            // final a_255 (scaled 2^-Dint) sits in q_sh[wid][0]
        } else {
            // ===== backward half: consume E_511..E_256 =======================
            // beta_511 = stop row of M; beta_{t-1} = M^T (E_t ∘ beta_t).
            float2 bp = make_float2(__expf(trans[STOP_TAG * TT + i0]),
                                    __expf(trans[STOP_TAG * TT + i1]));

            const float2* epb = ep2 + (LL - 1) * 32;
            float2 e0 = epb[0], e1 = epb[-1 * 32], e2 = epb[-2 * 32], e3 = epb[-3 * 32];

#pragma unroll 4
            for (int u = 0; u < HALF; ++u) {
                float2 e_pf = (u + 4 < HALF) ? epb[-(u + 4) * 32] : make_float2(0.f, 0.f);

                const float E0 = __expf(e0.x);
                const float E1 = __expf(e0.y);

                const float2 v = make_float2(E0 * bp.x, E1 * bp.y);  // E ∘ beta
                const int bu = u & 1;
                ((float2*)q_sh[wid][bu])[l] = v;
                __syncwarp();
                const float* qb = q_sh[wid][bu];

                const float v0 = qb[0];
                const unsigned ebits = __float_as_uint(v0) & 0x7f800000u;
                const float r = ebits ? __uint_as_float(0x7f000000u - ebits) : 1.0f;
                Dint += ebits ? ((int)(ebits >> 23) - 127) : 0;

                float s0, s1;
                dot64_pair(qb, P2a, P2b, s0, s1);   // columns: M^T v
                bp = make_float2(s0 * r, s1 * r);

                e0 = e1; e1 = e2; e2 = e3; e3 = e_pf;
            }

            // Publish beta_255 (scaled 2^-Dint) and Dint for the fwd partner.
            ((float2*)q_sh[wid][0])[l] = bp;
            if (l == 0) Db_sh[wid] = Dint;
        }
    } else {
        // ===== general masked path: fwd warp runs full 512-step log-space ====
        if (isFwd) {
            a0 = (i0 == START_TAG) ? 0.0f : -10000.0f;
            a1 = (i1 == START_TAG) ? 0.0f : -10000.0f;
            C  = 0.0f;
            for (int t = 0; t < LL; ++t) {
                const int bu = t & 1;
                ((float2*)q_sh[wid][bu])[l] = make_float2(__expf(a0), __expf(a1));
                __syncwarp();
                const float* qb = q_sh[wid][bu];

                const float mf = (float)mask[seq * LL + t];
                float s0, s1;
                if (mf != 0.0f) {
                    dot64_pair(qb, P2a, P2b, s0, s1);
                } else {
                    float acc = 0.f;
#pragma unroll
                    for (int j = 0; j < TT; ++j) acc += qb[j];
                    s0 = s1 = acc;
                }

                const float2 e = ep2[t * 32];
                float d0 = fmaf(mf, e.x, __logf(s0));
                float d1 = fmaf(mf, e.y, __logf(s1));
                d0 = fmaxf(d0, -1.0e30f);
                d1 = fmaxf(d1, -1.0e30f);
                const float anchor = __shfl_sync(FULLMASK, d0, 0);
                a0 = d0 - anchor;
                a1 = d1 - anchor;
                C += anchor;
                __syncwarp();
            }
        }
        // bwd warps idle to the block barrier
    }

    __syncthreads();

    if (isFwd) {
        float logden;
        if (all_ones) {
            // Z = sum_i a_255[i] * beta_255[i]  (both pow2-scaled; exact comp.)
            const float2 qf = ((const float2*)q_sh[wid][0])[l];
            const float* qbv = q_sh[wid + SPB][0];
            const float prod = qf.x * qbv[i0] + qf.y * qbv[i1];
            const float Z = warp_sum(prod);
            logden = __logf(Z) + (float)(Dint + Db_sh[wid + SPB]) * LN2F;
        } else {
            // terminal LSE from log-space alphas (proven R11 finale)
            float t0 = fmaxf(a0 + trans[STOP_TAG * TT + i0], -1.0e30f);
            float t1 = fmaxf(a1 + trans[STOP_TAG * TT + i1], -1.0e30f);
            const float mx = warp_max(fmaxf(t0, t1));
            const float sm = warp_sum(__expf(t0 - mx) + __expf(t1 - mx));
            logden = C + mx + __logf(sm);
        }

        // numerator path score (gold tags)
        float sc = 0.f;
        const float* in_b = inputs + (size_t)seq * LL * TT;
        const int*   tg   = tags + seq * LL;
        const int*   mk   = mask + seq * LL;
        for (int t = l; t < LL - 1; t += 32) {
            const int pt = tg[t];
            const int nt = tg[t + 1];
            sc += trans[nt * TT + pt] * (float)mk[t + 1]
                + in_b[t * TT + pt] * (float)mk[t];
        }
        sc = warp_sum(sc);
        if (l == 0) {
            const int tfirst = tg[0];
            const int tlast  = tg[LL - 1];
            float score = sc
                        + trans[tfirst * TT + START_TAG]
                        + trans[STOP_TAG * TT + tlast]
                        + in_b[(LL - 1) * TT + tlast] * (float)mk[LL - 1];
            g_partials[seq] = score - logden;
        }
    }

    // ---- deterministic fixed-order final reduction in the last block ----
    __syncthreads();
    if (tid == 0) {
        __threadfence();
        int old = atomicAdd(&g_count, 1);
        islast = (old == (int)gridDim.x - 1);
    }
    __syncthreads();
    if (islast) {
        __threadfence();
        float s = g_partials[tid * 2] + g_partials[tid * 2 + 1];  // 256 x 2, fixed order
        rf[tid] = s;
        __syncthreads();
#pragma unroll
        for (int off = (64 * SPB) / 2; off > 0; off >>= 1) {
            if (tid < off) rf[tid] += rf[tid + off];
            __syncthreads();
        }
        if (tid == 0) {
            out[0] = rf[0];
            g_count = 0;
        }
    }
}

extern "C" void kernel_launch(void* const* d_in, const int* in_sizes, int n_in,
                              void* d_out, int out_size)
{
    const float* inputs = (const float*)d_in[0];
    const int*   tags   = (const int*)d_in[1];
    const int*   mask   = (const int*)d_in[2];
    const float* trans  = (const float*)d_in[3];

    crf_fused_kernel<<<NBLK, 64 * SPB>>>(inputs, tags, mask, trans, (float*)d_out);
}

// round 17
// speedup vs baseline: 1.9235x; 1.1527x over previous
#include <cuda_runtime.h>
#include <cuda_bf16.h>
#include <cstdint>
#include <cstddef>

#define TT 64
#define LL 512
#define BB 512
#define START_TAG 62
#define STOP_TAG  63
#define SPB 4                  // sequences per block (8 warps: 4 fwd + 4 bwd)
#define NBLK (BB / SPB)        // 128 blocks
#define HALF (LL / 2)          // 256 steps per half-chain
#define LN2F 0.6931471805599453f
#define FULLMASK 0xffffffffu

// Scratch (allocation-free requirement).
__device__ float g_partials[BB];
__device__ int   g_count;      // zero-init; reset by last block each launch

__device__ __forceinline__ __nv_bfloat162 u2bf2(unsigned int x) {
    union { unsigned int u; __nv_bfloat162 h; } cv; cv.u = x; return cv.h;
}

__device__ __forceinline__ float warp_sum(float v) {
#pragma unroll
    for (int o = 16; o > 0; o >>= 1) v += __shfl_xor_sync(FULLMASK, v, o);
    return v;
}
__device__ __forceinline__ float warp_max(float v) {
#pragma unroll
    for (int o = 16; o > 0; o >>= 1) v = fmaxf(v, __shfl_xor_sync(FULLMASK, v, o));
    return v;
}

// ---- fp32 packed helpers (fallback path, R11/R14-proven) ----
__device__ __forceinline__ void fma2(unsigned long long& acc, unsigned long long p, unsigned long long q) {
    asm("fma.rn.f32x2 %0, %1, %2, %0;" : "+l"(acc) : "l"(p), "l"(q));
}
__device__ __forceinline__ void add2(unsigned long long& a, unsigned long long b) {
    asm("add.rn.f32x2 %0, %0, %1;" : "+l"(a) : "l"(b));
}
__device__ __forceinline__ float2 unpack2(unsigned long long v) {
    float2 r; asm("mov.b64 {%0, %1}, %2;" : "=f"(r.x), "=f"(r.y) : "l"(v)); return r;
}
__device__ __forceinline__ unsigned long long pack2(float lo, float hi) {
    unsigned long long v; asm("mov.b64 %0, {%1, %2};" : "=l"(v) : "f"(lo), "f"(hi)); return v;
}

__device__ __forceinline__ void dot64_pair_f32(const float* __restrict__ qbuf,
                                               const unsigned long long* __restrict__ P2a,
                                               const unsigned long long* __restrict__ P2b,
                                               float& s0, float& s1) {
    const ulonglong2* q4 = (const ulonglong2*)qbuf;
    unsigned long long a0 = 0, a1 = 0, b0 = 0, b1 = 0;
#pragma unroll
    for (int k = 0; k < 16; ++k) {
        ulonglong2 v = q4[k];
        fma2(a0, P2a[2 * k],     v.x);
        fma2(a1, P2a[2 * k + 1], v.y);
        fma2(b0, P2b[2 * k],     v.x);
        fma2(b1, P2b[2 * k + 1], v.y);
    }
    add2(a0, a1); add2(b0, b1);
    float2 pa = unpack2(a0), pb = unpack2(b0);
    s0 = pa.x + pa.y; s1 = pb.x + pb.y;
}

// bf16 dual 64-dot: word k of qbuf = (q[2k], q[2k+1]); Pa/Pb rows for tags i0/i1.
// 64 HFMA2 total; 2 accumulator chains of 16 per tag; fp32 combine.
__device__ __forceinline__ void dot64_pair_bf16(const __nv_bfloat162* __restrict__ qbuf,
                                                const __nv_bfloat162* __restrict__ Pa,
                                                const __nv_bfloat162* __restrict__ Pb,
                                                float& s0, float& s1) {
    const uint4* q4 = (const uint4*)qbuf;
    const __nv_bfloat162 z2 = __floats2bfloat162_rn(0.0f, 0.0f);
    __nv_bfloat162 A0 = z2, A1 = z2, B0 = z2, B1 = z2;
#pragma unroll
    for (int c = 0; c < 4; ++c) {            // words 0..15 -> chains A0/B0
        uint4 u = q4[c];
        __nv_bfloat162 w0 = u2bf2(u.x), w1 = u2bf2(u.y), w2 = u2bf2(u.z), w3 = u2bf2(u.w);
        A0 = __hfma2(Pa[4 * c + 0], w0, A0);  B0 = __hfma2(Pb[4 * c + 0], w0, B0);
        A0 = __hfma2(Pa[4 * c + 1], w1, A0);  B0 = __hfma2(Pb[4 * c + 1], w1, B0);
        A0 = __hfma2(Pa[4 * c + 2], w2, A0);  B0 = __hfma2(Pb[4 * c + 2], w2, B0);
        A0 = __hfma2(Pa[4 * c + 3], w3, A0);  B0 = __hfma2(Pb[4 * c + 3], w3, B0);
    }
#pragma unroll
    for (int c = 4; c < 8; ++c) {            // words 16..31 -> chains A1/B1
        uint4 u = q4[c];
        __nv_bfloat162 w0 = u2bf2(u.x), w1 = u2bf2(u.y), w2 = u2bf2(u.z), w3 = u2bf2(u.w);
        A1 = __hfma2(Pa[4 * c + 0], w0, A1);  B1 = __hfma2(Pb[4 * c + 0], w0, B1);
        A1 = __hfma2(Pa[4 * c + 1], w1, A1);  B1 = __hfma2(Pb[4 * c + 1], w1, B1);
        A1 = __hfma2(Pa[4 * c + 2], w2, A1);  B1 = __hfma2(Pb[4 * c + 2], w2, B1);
        A1 = __hfma2(Pa[4 * c + 3], w3, A1);  B1 = __hfma2(Pb[4 * c + 3], w3, B1);
    }
    const float2 fa0 = __bfloat1622float2(A0), fa1 = __bfloat1622float2(A1);
    const float2 fb0 = __bfloat1622float2(B0), fb1 = __bfloat1622float2(B1);
    s0 = (fa0.x + fa0.y) + (fa1.x + fa1.y);
    s1 = (fb0.x + fb0.y) + (fb1.x + fb1.y);
}

__global__ void __launch_bounds__(64 * SPB, 1) crf_fused_kernel(
    const float* __restrict__ inputs,   // (B, L, T)
    const int*   __restrict__ tags,     // (B, L)
    const int*   __restrict__ mask,     // (B, L)
    const float* __restrict__ trans,    // (T, T)
    float*       __restrict__ out)
{
    const int tid  = threadIdx.x;
    const int wid  = tid >> 5;
    const int l    = tid & 31;          // owns tags 2l, 2l+1
    const int i0   = 2 * l;
    const int i1   = 2 * l + 1;
    const int isFwd = (wid < SPB);
    const int sw   = wid & (SPB - 1);
    const int seq  = blockIdx.x * SPB + sw;

    __shared__ __align__(16) float q_sh[2 * SPB][2][TT];            // fallback fp32
    __shared__ __align__(16) __nv_bfloat162 qh[2 * SPB][2][TT / 2]; // fast bf16x2
    __shared__ int   Db_sh[2 * SPB];
    __shared__ float rf[64 * SPB];
    __shared__ int   islast;

    // all-ones mask detection for this warp's sequence (warp-local).
    int m_and = 1;
    for (int t = l; t < LL; t += 32)
        m_and &= (mask[seq * LL + t] != 0);
    const int all_ones = __all_sync(FULLMASK, m_and);

    // Emissions as float2 (tags 2l, 2l+1 contiguous): 32 float2 per step.
    const float2* ep2 = (const float2*)(inputs + (size_t)seq * LL * TT) + l;

    float a0 = 0.f, a1 = 0.f, C = 0.f;  // fallback outputs
    int Dint = 0;

    if (all_ones) {
        // ---- bf16 transition rows/columns for this thread's two tags --------
        __nv_bfloat162 Pa[TT / 2], Pb[TT / 2];
        if (isFwd) {
#pragma unroll
            for (int j = 0; j < TT / 2; ++j) {
                Pa[j] = __floats2bfloat162_rn(__expf(trans[i0 * TT + 2 * j]),
                                              __expf(trans[i0 * TT + 2 * j + 1]));
                Pb[j] = __floats2bfloat162_rn(__expf(trans[i1 * TT + 2 * j]),
                                              __expf(trans[i1 * TT + 2 * j + 1]));
            }
        } else {
#pragma unroll
            for (int j = 0; j < TT / 2; ++j) {
                Pa[j] = __floats2bfloat162_rn(__expf(trans[(2 * j) * TT + i0]),
                                              __expf(trans[(2 * j + 1) * TT + i0]));
                Pb[j] = __floats2bfloat162_rn(__expf(trans[(2 * j) * TT + i1]),
                                              __expf(trans[(2 * j + 1) * TT + i1]));
            }
        }

        if (isFwd) {
            // ===== forward half: consume E_0..E_255 ==========================
            qh[wid][0][l] = __floats2bfloat162_rn((i0 == START_TAG) ? 1.0f : 0.0f,
                                                  (i1 == START_TAG) ? 1.0f : 0.0f);

            float2 e0 = ep2[0 * 32], e1 = ep2[1 * 32], e2 = ep2[2 * 32], e3 = ep2[3 * 32];
            __syncwarp();

#pragma unroll 4
            for (int t = 0; t < HALF; ++t) {
                float2 e_pf = (t + 4 < HALF) ? ep2[(t + 4) * 32] : make_float2(0.f, 0.f);

                const float E0 = __expf(e0.x);
                const float E1 = __expf(e0.y);

                const int bu = t & 1;
                const __nv_bfloat162* qb = qh[wid][bu];

                const float q0 = __low2float(qb[0]);
                const unsigned ebits = __float_as_uint(q0) & 0x7f800000u;
                const float r = ebits ? __uint_as_float(0x7f000000u - ebits) : 1.0f;
                Dint += ebits ? ((int)(ebits >> 23) - 127) : 0;

                float s0, s1;
                dot64_pair_bf16(qb, Pa, Pb, s0, s1);
                qh[wid][bu ^ 1][l] = __floats2bfloat162_rn(s0 * (E0 * r), s1 * (E1 * r));
                __syncwarp();

                e0 = e1; e1 = e2; e2 = e3; e3 = e_pf;
            }
            // final alpha_255 (scaled 2^-Dint) sits in qh[wid][0]
        } else {
            // ===== backward half: consume E_511..E_256 =======================
            float2 bp = make_float2(__expf(trans[STOP_TAG * TT + i0]),
                                    __expf(trans[STOP_TAG * TT + i1]));

            const float2* epb = ep2 + (LL - 1) * 32;
            float2 e0 = epb[0], e1 = epb[-1 * 32], e2 = epb[-2 * 32], e3 = epb[-3 * 32];

#pragma unroll 4
            for (int u = 0; u < HALF; ++u) {
                float2 e_pf = (u + 4 < HALF) ? epb[-(u + 4) * 32] : make_float2(0.f, 0.f);

                const float E0 = __expf(e0.x);
                const float E1 = __expf(e0.y);

                const float2 v = make_float2(E0 * bp.x, E1 * bp.y);  // E ∘ beta
                const int bu = u & 1;
                qh[wid][bu][l] = __floats2bfloat162_rn(v.x, v.y);
                __syncwarp();
                const __nv_bfloat162* qb = qh[wid][bu];

                const float v0 = __low2float(qb[0]);
                const unsigned ebits = __float_as_uint(v0) & 0x7f800000u;
                const float r = ebits ? __uint_as_float(0x7f000000u - ebits) : 1.0f;
                Dint += ebits ? ((int)(ebits >> 23) - 127) : 0;

                float s0, s1;
                dot64_pair_bf16(qb, Pa, Pb, s0, s1);   // columns: M^T v
                bp = make_float2(s0 * r, s1 * r);

                e0 = e1; e1 = e2; e2 = e3; e3 = e_pf;
            }

            // Publish beta (scaled 2^-Dint) and Dint for the fwd partner.
            __syncwarp();
            qh[wid][0][l] = __floats2bfloat162_rn(bp.x, bp.y);
            if (l == 0) Db_sh[wid] = Dint;
        }
    } else {
        // ===== general masked path: fwd warp runs full 512-step log-space ====
        if (isFwd) {
            unsigned long long P2a[TT / 2], P2b[TT / 2];
#pragma unroll
            for (int j = 0; j < TT / 2; ++j) {
                P2a[j] = pack2(__expf(trans[i0 * TT + 2 * j]), __expf(trans[i0 * TT + 2 * j + 1]));
                P2b[j] = pack2(__expf(trans[i1 * TT + 2 * j]), __expf(trans[i1 * TT + 2 * j + 1]));
            }
            a0 = (i0 == START_TAG) ? 0.0f : -10000.0f;
            a1 = (i1 == START_TAG) ? 0.0f : -10000.0f;
            C  = 0.0f;
            for (int t = 0; t < LL; ++t) {
                const int bu = t & 1;
                ((float2*)q_sh[wid][bu])[l] = make_float2(__expf(a0), __expf(a1));
                __syncwarp();
                const float* qb = q_sh[wid][bu];

                const float mf = (float)mask[seq * LL + t];
                float s0, s1;
                if (mf != 0.0f) {
                    dot64_pair_f32(qb, P2a, P2b, s0, s1);
                } else {
                    float acc = 0.f;
#pragma unroll
                    for (int j = 0; j < TT; ++j) acc += qb[j];
                    s0 = s1 = acc;
                }

                const float2 e = ep2[t * 32];
                float d0 = fmaf(mf, e.x, __logf(s0));
                float d1 = fmaf(mf, e.y, __logf(s1));
                d0 = fmaxf(d0, -1.0e30f);
                d1 = fmaxf(d1, -1.0e30f);
                const float anchor = __shfl_sync(FULLMASK, d0, 0);
                a0 = d0 - anchor;
                a1 = d1 - anchor;
                C += anchor;
                __syncwarp();
            }
        }
        // bwd warps idle to the block barrier
    }

    __syncthreads();

    if (isFwd) {
        float logden;
        if (all_ones) {
            // Z = sum_i alpha_255[i] * beta_255[i] (both pow2-scaled; exact comp.)
            const float2 fa = __bfloat1622float2(qh[wid][0][l]);
            const float2 fb = __bfloat1622float2(qh[wid + SPB][0][l]);
            const float Z = warp_sum(fa.x * fb.x + fa.y * fb.y);
            logden = __logf(Z) + (float)(Dint + Db_sh[wid + SPB]) * LN2F;
        } else {
            float t0 = fmaxf(a0 + trans[STOP_TAG * TT + i0], -1.0e30f);
            float t1 = fmaxf(a1 + trans[STOP_TAG * TT + i1], -1.0e30f);
            const float mx = warp_max(fmaxf(t0, t1));
            const float sm = warp_sum(__expf(t0 - mx) + __expf(t1 - mx));
            logden = C + mx + __logf(sm);
        }

        // numerator path score (gold tags)
        float sc = 0.f;
        const float* in_b = inputs + (size_t)seq * LL * TT;
        const int*   tg   = tags + seq * LL;
        const int*   mk   = mask + seq * LL;
        for (int t = l; t < LL - 1; t += 32) {
            const int pt = tg[t];
            const int nt = tg[t + 1];
            sc += trans[nt * TT + pt] * (float)mk[t + 1]
                + in_b[t * TT + pt] * (float)mk[t];
        }
        sc = warp_sum(sc);
        if (l == 0) {
            const int tfirst = tg[0];
            const int tlast  = tg[LL - 1];
            float score = sc
                        + trans[tfirst * TT + START_TAG]
                        + trans[STOP_TAG * TT + tlast]
                        + in_b[(LL - 1) * TT + tlast] * (float)mk[LL - 1];
            g_partials[seq] = score - logden;
        }
    }

    // ---- deterministic fixed-order final reduction in the last block ----
    __syncthreads();
    if (tid == 0) {
        __threadfence();
        int old = atomicAdd(&g_count, 1);
        islast = (old == (int)gridDim.x - 1);
    }
    __syncthreads();
    if (islast) {
        __threadfence();
        float s = g_partials[tid * 2] + g_partials[tid * 2 + 1];  // 256 x 2, fixed order
        rf[tid] = s;
        __syncthreads();
#pragma unroll
        for (int off = (64 * SPB) / 2; off > 0; off >>= 1) {
            if (tid < off) rf[tid] += rf[tid + off];
            __syncthreads();
        }
        if (tid == 0) {
            out[0] = rf[0];
            g_count = 0;
        }
    }
}

extern "C" void kernel_launch(void* const* d_in, const int* in_sizes, int n_in,
                              void* d_out, int out_size)
{
    const float* inputs = (const float*)d_in[0];
    const int*   tags   = (const int*)d_in[1];
    const int*   mask   = (const int*)d_in[2];
    const float* trans  = (const float*)d_in[3];

    crf_fused_kernel<<<NBLK, 64 * SPB>>>(inputs, tags, mask, trans, (float*)d_out);
}